// round 1
// baseline (speedup 1.0000x reference)
#include <cuda_runtime.h>

// Problem constants (fixed shapes from reference)
constexpr int kB = 32;   // batch
constexpr int kA = 5;    // anchors
constexpr int kC = 8;    // classes
constexpr int kH = 32;
constexpr int kW = 64;
constexpr int kT = 50;   // targets
constexpr int kCh = 7 + kC;              // 15 channels per anchor
constexpr int kCellsPerB = kA * kH * kW; // 10240
constexpr float SIL = 0.6f;

__constant__ float c_aw[kA] = {1.08f, 3.42f, 6.63f, 9.42f, 16.62f};
__constant__ float c_al[kA] = {1.19f, 4.41f, 11.38f, 5.11f, 10.52f};

// Scratch (allocation-free: device globals)
__device__ int   g_cellmap[kB * kCellsPerB];   // -1 or (b*kT + t) index of assigned target
__device__ float g_tbox[kB * kT * 4];          // gx, gy, gw, gl per target (valid ones)
__device__ float g_tdata[kB * kT * 7];         // tx, ty, tw, tl, tim, tre, tcls(float)
__device__ int   g_nvalid[kB];

// ---------------------------------------------------------------------------
// Kernel 0: reset cellmap and zero the output scalar
// ---------------------------------------------------------------------------
__global__ void k_init(float* out, int out_size) {
    int idx = blockIdx.x * blockDim.x + threadIdx.x;
    if (idx < kB * kCellsPerB) g_cellmap[idx] = -1;
    if (idx < out_size) out[idx] = 0.0f;
}

// ---------------------------------------------------------------------------
// Kernel 1: per-target preprocessing. 1 block per batch, 1 thread per target.
// Computes validity (cumprod of tgt[...,1] != 0), best anchor (first argmax),
// cell assignment with segment_max dedupe (last valid target per cell wins),
// and the regression targets.
// ---------------------------------------------------------------------------
__global__ void k_prep(const float* __restrict__ tgt) {
    int b = blockIdx.x;
    int t = threadIdx.x;

    __shared__ int svalid[kT];
    __shared__ int slin[kT];
    __shared__ int sbn[kT];
    __shared__ int snv;

    const float* tr = tgt + ((size_t)b * kT + t) * 7;

    if (t < kT) svalid[t] = (tr[1] != 0.0f) ? 1 : 0;
    __syncthreads();

    if (t == 0) {
        int nv = 0;
        while (nv < kT && svalid[nv]) nv++;
        snv = nv;
        g_nvalid[b] = nv;
    }
    __syncthreads();
    int nv = snv;

    if (t < nv) {
        float gx = tr[1] * (float)kW;
        float gy = tr[2] * (float)kH;
        float gw = tr[3] * (float)kW;
        float gl = tr[4] * (float)kH;
        int gi = min(max((int)gx, 0), kW - 1);
        int gj = min(max((int)gy, 0), kH - 1);

        // anchor-IoU argmax (first max wins, like jnp.argmax)
        int best = 0;
        float bestv = -1e30f;
        float garea = gw * gl;
#pragma unroll
        for (int a = 0; a < kA; a++) {
            float inter = fminf(gw, c_aw[a]) * fminf(gl, c_al[a]);
            float uni = garea + c_aw[a] * c_al[a] - inter;
            float v = inter / uni;
            if (v > bestv) { bestv = v; best = a; }
        }
        sbn[t] = best;
        slin[t] = (best * kH + gj) * kW + gi;

        float* tb = g_tbox + ((size_t)b * kT + t) * 4;
        tb[0] = gx; tb[1] = gy; tb[2] = gw; tb[3] = gl;
    }
    __syncthreads();

    if (t < nv) {
        int mylin = slin[t];
        bool keep = true;
        for (int j2 = t + 1; j2 < nv; j2++)
            if (slin[j2] == mylin) { keep = false; break; }
        if (keep) {
            float gx = tr[1] * (float)kW;
            float gy = tr[2] * (float)kH;
            float gw = tr[3] * (float)kW;
            float gl = tr[4] * (float)kH;
            int gi = min(max((int)gx, 0), kW - 1);
            int gj = min(max((int)gy, 0), kH - 1);
            int bn = sbn[t];
            int idx = b * kT + t;
            float* td = g_tdata + (size_t)idx * 7;
            td[0] = gx - (float)gi;
            td[1] = gy - (float)gj;
            td[2] = logf(gw / c_aw[bn]);
            td[3] = logf(gl / c_al[bn]);
            td[4] = tr[5];
            td[5] = tr[6];
            td[6] = tr[0];                 // tcls (cast to int by consumer)
            g_cellmap[b * kCellsPerB + mylin] = idx;
        }
    }
}

// ---------------------------------------------------------------------------
// Kernel 2: main loss. 1 thread per cell (b, a, j, i). grid = (40, 32), 256 thr.
// ---------------------------------------------------------------------------
__global__ void __launch_bounds__(256) k_main(const float* __restrict__ out,
                                              float* __restrict__ loss) {
    int b = blockIdx.y;
    int tid = threadIdx.x;
    int cell = blockIdx.x * 256 + tid;      // 0..10239
    int a = cell >> 11;                     // /2048
    int rem = cell & 2047;                  // j*64 + i
    int i = rem & 63;
    int j = rem >> 6;

    __shared__ float sx1[kT], sx2[kT], sy1[kT], sy2[kT];
    __shared__ float ssw[kT], ssl[kT], sarea[kT];
    __shared__ int snv;

    if (tid == 0) snv = g_nvalid[b];
    if (tid < kT) {
        const float* tb = g_tbox + ((size_t)b * kT + tid) * 4;
        float gx = tb[0], gy = tb[1], gw = tb[2], gl = tb[3];
        sx1[tid] = gx - gw * 0.5f;
        sx2[tid] = gx + gw * 0.5f;
        sy1[tid] = gy - gl * 0.5f;
        sy2[tid] = gy + gl * 0.5f;
        ssw[tid] = gw;
        ssl[tid] = gl;
        sarea[tid] = gw * gl;
    }
    __syncthreads();

    // load the 15 channels for this cell (stride 2048 floats, coalesced over i)
    const float* base = out + ((size_t)b * (kA * kCh) + (size_t)a * kCh) * (kH * kW) + rem;
    float c[kCh];
#pragma unroll
    for (int q = 0; q < kCh; q++) c[q] = base[(size_t)q * (kH * kW)];

    float sxv  = 1.0f / (1.0f + __expf(-c[0]));
    float syv  = 1.0f / (1.0f + __expf(-c[1]));
    float conf = 1.0f / (1.0f + __expf(-c[6]));

    float px = sxv + (float)i;
    float py = syv + (float)j;
    float pw = __expf(c[2]) * c_aw[a];
    float pl = __expf(c[3]) * c_al[a];
    float px1 = px - pw * 0.5f, px2 = px + pw * 0.5f;
    float py1 = py - pl * 0.5f, py2 = py + pl * 0.5f;
    float parea = pw * pl;

    // exists-target-with-iou>0.6 test, division-free: inter > SIL * union
    bool found = false;
    int nv = snv;
    for (int t = 0; t < nv; t++) {
        float mx = fminf(px1, sx1[t]);
        float Mx = fmaxf(px2, sx2[t]);
        float my = fminf(py1, sy1[t]);
        float My = fmaxf(py2, sy2[t]);
        float cw = (pw + ssw[t]) - (Mx - mx);
        float ch = (pl + ssl[t]) - (My - my);
        if (cw > 0.0f && ch > 0.0f) {
            float inter = cw * ch;
            float uni = parea + sarea[t] - inter;
            found = found || (inter > SIL * uni);
        }
    }

    float acc;
    int map = g_cellmap[b * kCellsPerB + cell];
    if (map >= 0) {
        const float* td = g_tdata + (size_t)map * 7;
        float dx  = sxv - td[0];
        float dy  = syv - td[1];
        float dw  = c[2] - td[2];
        float dl  = c[3] - td[3];
        float dim_ = c[4] - td[4];
        float dre = c[5] - td[5];

        // tconf = iou(gt box, pred box at this cell)
        const float* tb = g_tbox + (size_t)map * 4;
        float gx = tb[0], gy = tb[1], gw = tb[2], gl = tb[3];
        float mx = fminf(px1, gx - gw * 0.5f);
        float Mx = fmaxf(px2, gx + gw * 0.5f);
        float my = fminf(py1, gy - gl * 0.5f);
        float My = fmaxf(py2, gy + gl * 0.5f);
        float cw = (pw + gw) - (Mx - mx);
        float ch = (pl + gl) - (My - my);
        float inter = (cw > 0.0f && ch > 0.0f) ? cw * ch : 0.0f;
        float uni = parea + gw * gl - inter;
        float tconf = inter / uni;
        float dconf = conf * 10.0f - tconf * 10.0f;   // OBJECT_SCALE inside square

        // cross-entropy over 8 class logits (max-subtracted logsumexp)
        float m = c[7];
#pragma unroll
        for (int q = 8; q < kCh; q++) m = fmaxf(m, c[q]);
        float s = 0.0f;
#pragma unroll
        for (int q = 7; q < kCh; q++) s += __expf(c[q] - m);
        int tcls = (int)td[6];
        float ce = m + logf(s) - c[7 + tcls];

        acc = dx * dx + dy * dy + dw * dw + dl * dl + dim_ * dim_ + dre * dre
            + dconf * dconf + ce;
    } else {
        // NOOBJECT_SCALE = 1 unless some target IoU > 0.6 (then mask 0)
        float cc = found ? 0.0f : conf;
        acc = cc * cc;
    }

    // block reduction + one atomic per block
    __shared__ float red[256];
    red[tid] = acc;
    __syncthreads();
#pragma unroll
    for (int s2 = 128; s2 > 0; s2 >>= 1) {
        if (tid < s2) red[tid] += red[tid + s2];
        __syncthreads();
    }
    if (tid == 0) atomicAdd(loss, red[0]);
}

// ---------------------------------------------------------------------------
extern "C" void kernel_launch(void* const* d_in, const int* in_sizes, int n_in,
                              void* d_out, int out_size) {
    const float* output = (const float*)d_in[0];
    const float* target = (const float*)d_in[1];
    float* loss = (float*)d_out;

    int initN = kB * kCellsPerB;
    k_init<<<(initN + 255) / 256, 256>>>(loss, out_size);
    k_prep<<<kB, 64>>>(target);
    dim3 grid(kCellsPerB / 256, kB);
    k_main<<<grid, 256>>>(output, loss);
}

// round 2
// speedup vs baseline: 1.2439x; 1.2439x over previous
#include <cuda_runtime.h>

constexpr int kB = 32;
constexpr int kA = 5;
constexpr int kC = 8;
constexpr int kH = 32;
constexpr int kW = 64;
constexpr int kT = 50;
constexpr int kCh = 7 + kC;              // 15
constexpr int kHW = kH * kW;             // 2048
constexpr int kCellsPerB = kA * kHW;     // 10240
constexpr int kBlocksPerB = kCellsPerB / 256;   // 40
constexpr int kGrid = kB * kBlocksPerB;         // 1280

__constant__ float c_aw[kA] = {1.08f, 3.42f, 6.63f, 9.42f, 16.62f};
__constant__ float c_al[kA] = {1.19f, 4.41f, 11.38f, 5.11f, 10.52f};

__device__ float        g_partials[kGrid];
__device__ unsigned int g_count = 0;      // self-resetting: deterministic across graph replays

__global__ void __launch_bounds__(256) k_fused(const float* __restrict__ out,
                                               const float* __restrict__ tgt,
                                               float* __restrict__ loss,
                                               int out_size) {
    const int tid = threadIdx.x;
    const int bid = blockIdx.x;
    const int b   = bid / kBlocksPerB;
    const int cb  = bid - b * kBlocksPerB;
    const int cell = cb * 256 + tid;          // 0..10239 within batch
    const int a   = cell >> 11;               // anchor
    const int rem = cell & 2047;              // j*64+i
    const int i   = rem & 63;
    const int j   = rem >> 6;

    // ---------------- per-batch target prep (redundant per block, tiny) ----
    __shared__ float4 sbox[kT];               // x1, y1, x2, y2
    __shared__ float2 saux[kT];               // { -0.6*area, int_as_float(kept_lin or -1) }
    __shared__ float  std_[kT][8];            // tx, ty, tw, tl, tim, tre, tcls
    __shared__ int    s_lin[kT];
    __shared__ int    s_valid[kT];
    __shared__ int    s_nv;

    if (tid < kT) {
        const float* tr = tgt + ((size_t)b * kT + tid) * 7;
        float t0 = tr[0], t1 = tr[1], t2 = tr[2], t3 = tr[3];
        float t4 = tr[4], t5 = tr[5], t6 = tr[6];
        s_valid[tid] = (t1 != 0.0f) ? 1 : 0;

        float gx = t1 * (float)kW;
        float gy = t2 * (float)kH;
        float gw = t3 * (float)kW;
        float gl = t4 * (float)kH;
        int gi = min(max((int)gx, 0), kW - 1);
        int gj = min(max((int)gy, 0), kH - 1);

        int best = 0; float bestv = -1e30f;
        float garea = gw * gl;
#pragma unroll
        for (int q = 0; q < kA; q++) {
            float inter = fminf(gw, c_aw[q]) * fminf(gl, c_al[q]);
            float uni = garea + c_aw[q] * c_al[q] - inter;
            float v = inter / uni;
            if (v > bestv) { bestv = v; best = q; }
        }
        s_lin[tid] = (best * kH + gj) * kW + gi;

        sbox[tid] = make_float4(gx - gw * 0.5f, gy - gl * 0.5f,
                                gx + gw * 0.5f, gy + gl * 0.5f);
        saux[tid].x = -0.6f * garea;

        std_[tid][0] = gx - (float)gi;
        std_[tid][1] = gy - (float)gj;
        std_[tid][2] = logf(gw / c_aw[best]);
        std_[tid][3] = logf(gl / c_al[best]);
        std_[tid][4] = t5;
        std_[tid][5] = t6;
        std_[tid][6] = t0;
    }
    __syncthreads();
    if (tid == 0) {
        int nv = 0;
        while (nv < kT && s_valid[nv]) nv++;
        s_nv = nv;
    }
    __syncthreads();
    const int nv = s_nv;
    if (tid < kT) {
        bool kept = (tid < nv);
        int mylin = s_lin[tid];
        for (int t2_ = tid + 1; t2_ < nv; t2_++)
            if (s_lin[t2_] == mylin) { kept = false; break; }
        saux[tid].y = __int_as_float(kept ? mylin : -1);
    }
    __syncthreads();

    // ---------------- per-cell work ---------------------------------------
    const float* base = out + ((size_t)(b * kA + a) * kCh) * kHW + rem;
    float c0 = base[0 * kHW];
    float c1 = base[1 * kHW];
    float c2 = base[2 * kHW];
    float c3 = base[3 * kHW];
    float c4 = base[4 * kHW];
    float c5 = base[5 * kHW];
    float c6 = base[6 * kHW];

    float sxv  = 1.0f / (1.0f + __expf(-c0));
    float syv  = 1.0f / (1.0f + __expf(-c1));
    float conf = 1.0f / (1.0f + __expf(-c6));

    float px = sxv + (float)i;
    float py = syv + (float)j;
    float pw = __expf(c2) * c_aw[a];
    float pl = __expf(c3) * c_al[a];
    float px1 = px - pw * 0.5f, px2 = px + pw * 0.5f;
    float py1 = py - pl * 0.5f, py2 = py + pl * 0.5f;
    float parea = pw * pl;
    float pa06  = 0.6f * parea;

    // exists(iou > 0.6) test + cell->target match, fused
    float best_m = -1e30f;
    int map = -1;
#pragma unroll 5
    for (int t = 0; t < nv; t++) {
        float4 bx = sbox[t];
        float2 ax = saux[t];
        float cw = fminf(px2, bx.z) - fmaxf(px1, bx.x);
        float ch = fminf(py2, bx.w) - fmaxf(py1, bx.y);
        float inter = fmaxf(cw, 0.0f) * fmaxf(ch, 0.0f);
        float m = fmaf(1.6f, inter, ax.x);
        best_m = fmaxf(best_m, m);
        if (__float_as_int(ax.y) == cell) map = t;
    }
    bool found = best_m > pa06;

    float acc;
    if (map >= 0) {
        float dx  = sxv - std_[map][0];
        float dy  = syv - std_[map][1];
        float dw  = c2  - std_[map][2];
        float dl  = c3  - std_[map][3];
        float dim_ = c4 - std_[map][4];
        float dre = c5  - std_[map][5];

        float4 bx = sbox[map];
        float cw = fminf(px2, bx.z) - fmaxf(px1, bx.x);
        float ch = fminf(py2, bx.w) - fmaxf(py1, bx.y);
        float inter = fmaxf(cw, 0.0f) * fmaxf(ch, 0.0f);
        float gw = bx.z - bx.x, gl = bx.w - bx.y;
        float uni = parea + gw * gl - inter;
        float tconf = inter / uni;
        float dconf = conf * 10.0f - tconf * 10.0f;

        // lazy class-logit load (matched cells only)
        float cl[kC];
#pragma unroll
        for (int q = 0; q < kC; q++) cl[q] = base[(size_t)(7 + q) * kHW];
        float mx = cl[0];
#pragma unroll
        for (int q = 1; q < kC; q++) mx = fmaxf(mx, cl[q]);
        float s = 0.0f;
#pragma unroll
        for (int q = 0; q < kC; q++) s += __expf(cl[q] - mx);
        int tcls = (int)std_[map][6];
        float ce = mx + logf(s) - cl[tcls];

        acc = dx * dx + dy * dy + dw * dw + dl * dl + dim_ * dim_ + dre * dre
            + dconf * dconf + ce;
    } else {
        float cc = found ? 0.0f : conf;
        acc = cc * cc;
    }

    // ---------------- reduction -------------------------------------------
    __shared__ float red[256];
    red[tid] = acc;
    __syncthreads();
#pragma unroll
    for (int s2 = 128; s2 > 0; s2 >>= 1) {
        if (tid < s2) red[tid] += red[tid + s2];
        __syncthreads();
    }

    __shared__ bool s_last;
    if (tid == 0) {
        g_partials[bid] = red[0];
        __threadfence();
        unsigned int r = atomicAdd(&g_count, 1u);
        s_last = (r == (unsigned)(kGrid - 1));
    }
    __syncthreads();

    if (s_last) {
        float s = 0.0f;
        for (int p = tid; p < kGrid; p += 256) s += __ldcg(&g_partials[p]);
        red[tid] = s;
        __syncthreads();
#pragma unroll
        for (int s2 = 128; s2 > 0; s2 >>= 1) {
            if (tid < s2) red[tid] += red[tid + s2];
            __syncthreads();
        }
        if (tid == 0) {
            loss[0] = red[0];
            g_count = 0;                 // self-reset for next replay
        }
        for (int p = 1 + tid; p < out_size; p += 256) loss[p] = 0.0f;
    }
}

extern "C" void kernel_launch(void* const* d_in, const int* in_sizes, int n_in,
                              void* d_out, int out_size) {
    const float* output = (const float*)d_in[0];
    const float* target = (const float*)d_in[1];
    k_fused<<<kGrid, 256>>>(output, target, (float*)d_out, out_size);
}

// round 3
// speedup vs baseline: 1.3472x; 1.0830x over previous
#include <cuda_runtime.h>

constexpr int kB = 32;
constexpr int kA = 5;
constexpr int kC = 8;
constexpr int kH = 32;
constexpr int kW = 64;
constexpr int kT = 50;
constexpr int kCh = 7 + kC;                    // 15
constexpr int kHW = kH * kW;                   // 2048
constexpr int kCellsPerB = kA * kHW;           // 10240
constexpr int kCellsPerBlock = 512;            // 2 cells per thread, 256 threads
constexpr int kBlocksPerB = kCellsPerB / kCellsPerBlock;   // 20
constexpr int kGrid = kB * kBlocksPerB;                    // 640

__constant__ float c_aw[kA] = {1.08f, 3.42f, 6.63f, 9.42f, 16.62f};
__constant__ float c_al[kA] = {1.19f, 4.41f, 11.38f, 5.11f, 10.52f};

__device__ float        g_partials[kGrid];
__device__ unsigned int g_count = 0;   // self-resets each run -> graph-replay deterministic

struct SmemT {
    float4 sbox[kT];        // x1, 1.6*y1, x2, 1.6*y2
    float  sna[kT];         // -0.6 * target_area
    float  std_[kT][8];     // tx, ty, tw, tl, tim, tre, tcls
    short  s_map[kCellsPerBlock];
    int    s_lin[kT];
    int    s_valid[kT];
    int    s_nv;
    float  red[256];
    bool   s_last;
};

// matched-cell loss (rare path: <= 50 cells per batch)
__device__ __forceinline__ float matched_loss(
    int m, const float* c, const float* base,
    float sxv, float syv, float conf,
    float px1, float px2, float py1s, float py2s, float parea,
    const SmemT* sm)
{
    float dx   = sxv  - sm->std_[m][0];
    float dy   = syv  - sm->std_[m][1];
    float dw   = c[2] - sm->std_[m][2];
    float dl   = c[3] - sm->std_[m][3];
    float dim_ = c[4] - sm->std_[m][4];
    float dre  = c[5] - sm->std_[m][5];

    float4 bx = sm->sbox[m];
    float cw  = fminf(px2, bx.z) - fmaxf(px1, bx.x);
    float chs = fminf(py2s, bx.w) - fmaxf(py1s, bx.y);     // 1.6*ch
    float inter = fmaxf(cw, 0.0f) * fmaxf(chs, 0.0f) * 0.625f;
    float gw = bx.z - bx.x;
    float gl = (bx.w - bx.y) * 0.625f;
    float uni = parea + gw * gl - inter;
    float tconf = inter / uni;
    float dconf = conf * 10.0f - tconf * 10.0f;

    float cl[kC];
#pragma unroll
    for (int q = 0; q < kC; q++) cl[q] = base[(size_t)(7 + q) * kHW];
    float mx = cl[0];
#pragma unroll
    for (int q = 1; q < kC; q++) mx = fmaxf(mx, cl[q]);
    float s = 0.0f;
#pragma unroll
    for (int q = 0; q < kC; q++) s += __expf(cl[q] - mx);
    int tcls = (int)sm->std_[m][6];
    float ce = mx + logf(s) - cl[tcls];

    return dx * dx + dy * dy + dw * dw + dl * dl + dim_ * dim_ + dre * dre
         + dconf * dconf + ce;
}

__global__ void __launch_bounds__(256, 4) k_fused(const float* __restrict__ out,
                                                  const float* __restrict__ tgt,
                                                  float* __restrict__ loss,
                                                  int out_size) {
    __shared__ SmemT sm;
    const int tid = threadIdx.x;
    const int bid = blockIdx.x;
    const int b   = bid / kBlocksPerB;
    const int cb  = bid - b * kBlocksPerB;
    const int cellbase = cb * kCellsPerBlock;
    const int cell0 = cellbase + tid;          // cell1 = cell0 + 256, same anchor
    const int a   = cell0 >> 11;
    const int rem0 = cell0 & 2047;
    const int i  = rem0 & 63;
    const int j0 = rem0 >> 6;
    const int j1 = j0 + 4;

    // issue the 14 channel LDGs up front (overlap with prep)
    const float* base0 = out + ((size_t)(b * kA + a) * kCh) * kHW + rem0;
    const float* base1 = base0 + 256;
    float cA[7], cB[7];
#pragma unroll
    for (int q = 0; q < 7; q++) cA[q] = base0[(size_t)q * kHW];
#pragma unroll
    for (int q = 0; q < 7; q++) cB[q] = base1[(size_t)q * kHW];

    // ---------------- per-batch target prep (tiny, per block) --------------
    sm.s_map[tid] = -1;
    sm.s_map[tid + 256] = -1;
    if (tid < kT) {
        const float* tr = tgt + ((size_t)b * kT + tid) * 7;
        float t0 = tr[0], t1 = tr[1], t2 = tr[2], t3 = tr[3];
        float t4 = tr[4], t5 = tr[5], t6 = tr[6];
        sm.s_valid[tid] = (t1 != 0.0f) ? 1 : 0;

        float gx = t1 * (float)kW;
        float gy = t2 * (float)kH;
        float gw = t3 * (float)kW;
        float gl = t4 * (float)kH;
        int gi = min(max((int)gx, 0), kW - 1);
        int gj = min(max((int)gy, 0), kH - 1);

        int best = 0; float bestv = -1e30f;
        float garea = gw * gl;
#pragma unroll
        for (int q = 0; q < kA; q++) {
            float inter = fminf(gw, c_aw[q]) * fminf(gl, c_al[q]);
            float uni = garea + c_aw[q] * c_al[q] - inter;
            float v = inter / uni;
            if (v > bestv) { bestv = v; best = q; }
        }
        sm.s_lin[tid] = (best * kH + gj) * kW + gi;

        sm.sbox[tid] = make_float4(gx - gw * 0.5f, 1.6f * (gy - gl * 0.5f),
                                   gx + gw * 0.5f, 1.6f * (gy + gl * 0.5f));
        sm.sna[tid] = -0.6f * garea;

        sm.std_[tid][0] = gx - (float)gi;
        sm.std_[tid][1] = gy - (float)gj;
        sm.std_[tid][2] = logf(gw / c_aw[best]);
        sm.std_[tid][3] = logf(gl / c_al[best]);
        sm.std_[tid][4] = t5;
        sm.std_[tid][5] = t6;
        sm.std_[tid][6] = t0;
    }
    __syncthreads();
    if (tid == 0) {
        int nv = 0;
        while (nv < kT && sm.s_valid[nv]) nv++;
        sm.s_nv = nv;
    }
    __syncthreads();
    const int nv = sm.s_nv;
    if (tid < nv) {
        int mylin = sm.s_lin[tid];
        bool kept = true;
        for (int t2_ = tid + 1; t2_ < nv; t2_++)
            if (sm.s_lin[t2_] == mylin) { kept = false; break; }
        int off = mylin - cellbase;
        if (kept && off >= 0 && off < kCellsPerBlock)
            sm.s_map[off] = (short)tid;
    }
    __syncthreads();

    // ---------------- per-cell derived values ------------------------------
    float sxv0  = 1.0f / (1.0f + __expf(-cA[0]));
    float syv0  = 1.0f / (1.0f + __expf(-cA[1]));
    float conf0 = 1.0f / (1.0f + __expf(-cA[6]));
    float sxv1  = 1.0f / (1.0f + __expf(-cB[0]));
    float syv1  = 1.0f / (1.0f + __expf(-cB[1]));
    float conf1 = 1.0f / (1.0f + __expf(-cB[6]));

    float pw0 = __expf(cA[2]) * c_aw[a];
    float pl0 = __expf(cA[3]) * c_al[a];
    float pw1 = __expf(cB[2]) * c_aw[a];
    float pl1 = __expf(cB[3]) * c_al[a];

    float px0 = sxv0 + (float)i,  py0 = syv0 + (float)j0;
    float px1_ = sxv1 + (float)i, py1_ = syv1 + (float)j1;

    float ax1_0 = px0 - pw0 * 0.5f, ax2_0 = px0 + pw0 * 0.5f;
    float ay1s0 = 1.6f * (py0 - pl0 * 0.5f), ay2s0 = 1.6f * (py0 + pl0 * 0.5f);
    float ax1_1 = px1_ - pw1 * 0.5f, ax2_1 = px1_ + pw1 * 0.5f;
    float ay1s1 = 1.6f * (py1_ - pl1 * 0.5f), ay2s1 = 1.6f * (py1_ + pl1 * 0.5f);

    float parea0 = pw0 * pl0, parea1 = pw1 * pl1;
    float th0 = 0.6f * parea0, th1 = 0.6f * parea1;

    // ---------------- exists(iou > 0.6) over targets, 2 cells per iter -----
    float best0 = -1e30f, best1 = -1e30f;
#pragma unroll 5
    for (int t = 0; t < nv; t++) {
        float4 bx = sm.sbox[t];
        float  na = sm.sna[t];
        float cw0 = fminf(ax2_0, bx.z) - fmaxf(ax1_0, bx.x);
        float ch0 = fminf(ay2s0, bx.w) - fmaxf(ay1s0, bx.y);
        best0 = fmaxf(best0, fmaf(fmaxf(cw0, 0.0f), ch0, na));
        float cw1 = fminf(ax2_1, bx.z) - fmaxf(ax1_1, bx.x);
        float ch1 = fminf(ay2s1, bx.w) - fmaxf(ay1s1, bx.y);
        best1 = fmaxf(best1, fmaf(fmaxf(cw1, 0.0f), ch1, na));
    }

    int map0 = sm.s_map[tid];
    int map1 = sm.s_map[tid + 256];

    float acc0, acc1;
    if (map0 >= 0) {
        acc0 = matched_loss(map0, cA, base0, sxv0, syv0, conf0,
                            ax1_0, ax2_0, ay1s0, ay2s0, parea0, &sm);
    } else {
        float cc = (best0 > th0) ? 0.0f : conf0;
        acc0 = cc * cc;
    }
    if (map1 >= 0) {
        acc1 = matched_loss(map1, cB, base1, sxv1, syv1, conf1,
                            ax1_1, ax2_1, ay1s1, ay2s1, parea1, &sm);
    } else {
        float cc = (best1 > th1) ? 0.0f : conf1;
        acc1 = cc * cc;
    }

    // ---------------- reduction -------------------------------------------
    sm.red[tid] = acc0 + acc1;
    __syncthreads();
#pragma unroll
    for (int s2 = 128; s2 > 0; s2 >>= 1) {
        if (tid < s2) sm.red[tid] += sm.red[tid + s2];
        __syncthreads();
    }

    if (tid == 0) {
        g_partials[bid] = sm.red[0];
        __threadfence();
        unsigned int r = atomicAdd(&g_count, 1u);
        sm.s_last = (r == (unsigned)(kGrid - 1));
    }
    __syncthreads();

    if (sm.s_last) {
        float s = 0.0f;
        for (int p = tid; p < kGrid; p += 256) s += __ldcg(&g_partials[p]);
        sm.red[tid] = s;
        __syncthreads();
#pragma unroll
        for (int s2 = 128; s2 > 0; s2 >>= 1) {
            if (tid < s2) sm.red[tid] += sm.red[tid + s2];
            __syncthreads();
        }
        if (tid == 0) {
            loss[0] = sm.red[0];
            g_count = 0;
        }
        for (int p = 1 + tid; p < out_size; p += 256) loss[p] = 0.0f;
    }
}

extern "C" void kernel_launch(void* const* d_in, const int* in_sizes, int n_in,
                              void* d_out, int out_size) {
    const float* output = (const float*)d_in[0];
    const float* target = (const float*)d_in[1];
    k_fused<<<kGrid, 256>>>(output, target, (float*)d_out, out_size);
}

// round 4
// speedup vs baseline: 1.6260x; 1.2070x over previous
#include <cuda_runtime.h>

constexpr int kB = 32;
constexpr int kA = 5;
constexpr int kC = 8;
constexpr int kH = 32;
constexpr int kW = 64;
constexpr int kT = 50;
constexpr int kCh = 7 + kC;                 // 15
constexpr int kHW = kH * kW;                // 2048
constexpr int kCellsPerB = kA * kHW;        // 10240
constexpr int kCellsPerBlock = 256;         // 1 cell/thread, block = 4 rows of one anchor
constexpr int kBlocksPerB = kCellsPerB / kCellsPerBlock;  // 40
constexpr int kGrid = kB * kBlocksPerB;                   // 1280

__constant__ float c_aw[kA] = {1.08f, 3.42f, 6.63f, 9.42f, 16.62f};
__constant__ float c_al[kA] = {1.19f, 4.41f, 11.38f, 5.11f, 10.52f};

__device__ float        g_partials[kGrid];
__device__ unsigned int g_count = 0;   // self-resets -> deterministic across graph replays

struct SmemT {
    float4   sbox[kT];          // original-index boxes: x1, 1.6*y1, x2, 1.6*y2 (matched path)
    float4   cbox[kT];          // compacted (culled) boxes
    float    cna[kT];           // compacted -0.6*area
    float    std_[kT][8];       // tx, ty, tw, tl, tim, tre, tcls (written for kept-in-block only)
    int      s_lin[kT];
    unsigned s_mask[2];
    short    s_map[kCellsPerBlock];
    int      s_cnt;
    float    red[256];
    bool     s_last;
};

__global__ void __launch_bounds__(256) k_fused(const float* __restrict__ out,
                                               const float* __restrict__ tgt,
                                               float* __restrict__ loss,
                                               int out_size) {
    __shared__ SmemT sm;
    const int tid = threadIdx.x;
    const int bid = blockIdx.x;
    const int b   = bid / kBlocksPerB;
    const int cb  = bid - b * kBlocksPerB;
    const int cellbase = cb * kCellsPerBlock;
    const int cell = cellbase + tid;
    const int a   = cell >> 11;
    const int rem = cell & 2047;
    const int i   = rem & 63;
    const int j   = rem >> 6;
    const int jlo = (cellbase & 2047) >> 6;      // block covers rows jlo..jlo+3

    // issue the 7 channel LDGs up front (overlap latency with prep)
    const float* base = out + ((size_t)(b * kA + a) * kCh) * kHW + rem;
    float c0 = base[0 * kHW];
    float c1 = base[1 * kHW];
    float c2 = base[2 * kHW];
    float c3 = base[3 * kHW];
    float c4 = base[4 * kHW];
    float c5 = base[5 * kHW];
    float c6 = base[6 * kHW];

    // ---------------- per-batch target prep --------------------------------
    sm.s_map[tid] = -1;
    if (tid == 0) sm.s_cnt = 0;

    float gx = 0.f, gy = 0.f, gw = 0.f, gl = 0.f, garea = 0.f;
    float t0 = 0.f, t5 = 0.f, t6 = 0.f;
    int gi = 0, gj = 0, besta = 0;
    float4 mybox = make_float4(0.f, 0.f, 0.f, 0.f);
    bool validt = false;
    if (tid < kT) {
        const float* tr = tgt + ((size_t)b * kT + tid) * 7;
        t0 = tr[0];
        float t1 = tr[1], t2 = tr[2], t3 = tr[3], t4 = tr[4];
        t5 = tr[5]; t6 = tr[6];
        validt = (t1 != 0.0f);

        gx = t1 * (float)kW;
        gy = t2 * (float)kH;
        gw = t3 * (float)kW;
        gl = t4 * (float)kH;
        gi = min(max((int)gx, 0), kW - 1);
        gj = min(max((int)gy, 0), kH - 1);
        garea = gw * gl;

        float bestv = -1e30f;
#pragma unroll
        for (int q = 0; q < kA; q++) {
            float inter = fminf(gw, c_aw[q]) * fminf(gl, c_al[q]);
            float uni = garea + c_aw[q] * c_al[q] - inter;
            float v = inter / uni;
            if (v > bestv) { bestv = v; besta = q; }
        }
        sm.s_lin[tid] = (besta * kH + gj) * kW + gi;

        mybox = make_float4(gx - gw * 0.5f, 1.6f * (gy - gl * 0.5f),
                            gx + gw * 0.5f, 1.6f * (gy + gl * 0.5f));
        sm.sbox[tid] = mybox;
    }
    unsigned bm = __ballot_sync(0xffffffffu, validt);
    if ((tid & 31) == 0 && (tid >> 5) < 2) sm.s_mask[tid >> 5] = bm;
    __syncthreads();

    unsigned long long mm = (unsigned long long)sm.s_mask[0]
                          | ((unsigned long long)sm.s_mask[1] << 32);
    const int nv = __ffsll((long long)~mm) - 1;   // first-zero index = cumprod validity

    if (tid < nv) {
        // segment_max dedupe: last valid target per cell wins
        int mylin = sm.s_lin[tid];
        bool kept = true;
        for (int u = tid + 1; u < nv; u++)
            if (sm.s_lin[u] == mylin) { kept = false; break; }
        int off = mylin - cellbase;
        if (kept && off >= 0 && off < kCellsPerBlock) {
            sm.s_map[off] = (short)tid;
            sm.std_[tid][0] = gx - (float)gi;
            sm.std_[tid][1] = gy - (float)gj;
            sm.std_[tid][2] = logf(gw / c_aw[besta]);
            sm.std_[tid][3] = logf(gl / c_al[besta]);
            sm.std_[tid][4] = t5;
            sm.std_[tid][5] = t6;
            sm.std_[tid][6] = t0;
        }
        // y-distance culling: IoU>0.6 requires |py-ty| < tl/3; py in (jlo, jlo+4)
        float tl3 = gl * (1.0f / 3.0f) + 1e-3f;
        if (gy + tl3 > (float)jlo && gy - tl3 < (float)(jlo + 4)) {
            int p = atomicAdd(&sm.s_cnt, 1);
            sm.cbox[p] = mybox;
            sm.cna[p]  = -0.6f * garea;
        }
    }
    __syncthreads();

    // ---------------- per-cell derived values -------------------------------
    float sxv  = 1.0f / (1.0f + __expf(-c0));
    float syv  = 1.0f / (1.0f + __expf(-c1));
    float conf = 1.0f / (1.0f + __expf(-c6));

    float pw = __expf(c2) * c_aw[a];
    float pl = __expf(c3) * c_al[a];
    float px = sxv + (float)i;
    float py = syv + (float)j;

    float x1 = px - pw * 0.5f, x2 = px + pw * 0.5f;
    float y1s = 1.6f * (py - pl * 0.5f), y2s = 1.6f * (py + pl * 0.5f);
    float parea = pw * pl;
    float th = 0.6f * parea;

    // ---------------- exists(iou > 0.6) over compacted targets --------------
    const int nc = sm.s_cnt;
    float bA = -1e30f, bB = -1e30f;
    int t = 0;
    for (; t + 2 <= nc; t += 2) {
        float4 q0 = sm.cbox[t];
        float  n0 = sm.cna[t];
        float4 q1 = sm.cbox[t + 1];
        float  n1 = sm.cna[t + 1];
        float cw0 = fminf(x2, q0.z) - fmaxf(x1, q0.x);
        float ch0 = fminf(y2s, q0.w) - fmaxf(y1s, q0.y);
        bA = fmaxf(bA, fmaf(fmaxf(cw0, 0.0f), ch0, n0));
        float cw1 = fminf(x2, q1.z) - fmaxf(x1, q1.x);
        float ch1 = fminf(y2s, q1.w) - fmaxf(y1s, q1.y);
        bB = fmaxf(bB, fmaf(fmaxf(cw1, 0.0f), ch1, n1));
    }
    if (t < nc) {
        float4 q0 = sm.cbox[t];
        float  n0 = sm.cna[t];
        float cw0 = fminf(x2, q0.z) - fmaxf(x1, q0.x);
        float ch0 = fminf(y2s, q0.w) - fmaxf(y1s, q0.y);
        bA = fmaxf(bA, fmaf(fmaxf(cw0, 0.0f), ch0, n0));
    }
    bool found = fmaxf(bA, bB) > th;

    const int map = sm.s_map[tid];
    float acc;
    if (map >= 0) {
        float dx   = sxv - sm.std_[map][0];
        float dy   = syv - sm.std_[map][1];
        float dw   = c2  - sm.std_[map][2];
        float dl   = c3  - sm.std_[map][3];
        float dim_ = c4  - sm.std_[map][4];
        float dre  = c5  - sm.std_[map][5];

        float4 bx = sm.sbox[map];
        float cw  = fminf(x2, bx.z) - fmaxf(x1, bx.x);
        float chs = fminf(y2s, bx.w) - fmaxf(y1s, bx.y);
        float inter = fmaxf(cw, 0.0f) * fmaxf(chs, 0.0f) * 0.625f;
        float tgw = bx.z - bx.x;
        float tgl = (bx.w - bx.y) * 0.625f;
        float uni = parea + tgw * tgl - inter;
        float tconf = inter / uni;
        float dconf = conf * 10.0f - tconf * 10.0f;

        // lazy class-logit loads: matched cells only
        float cl[kC];
#pragma unroll
        for (int q = 0; q < kC; q++) cl[q] = base[(size_t)(7 + q) * kHW];
        float mx = cl[0];
#pragma unroll
        for (int q = 1; q < kC; q++) mx = fmaxf(mx, cl[q]);
        float s = 0.0f;
#pragma unroll
        for (int q = 0; q < kC; q++) s += __expf(cl[q] - mx);
        int tcls = (int)sm.std_[map][6];
        float ce = mx + logf(s) - cl[tcls];

        acc = dx * dx + dy * dy + dw * dw + dl * dl + dim_ * dim_ + dre * dre
            + dconf * dconf + ce;
    } else {
        float cc = found ? 0.0f : conf;
        acc = cc * cc;
    }

    // ---------------- reduction ---------------------------------------------
    sm.red[tid] = acc;
    __syncthreads();
#pragma unroll
    for (int s2 = 128; s2 > 0; s2 >>= 1) {
        if (tid < s2) sm.red[tid] += sm.red[tid + s2];
        __syncthreads();
    }

    if (tid == 0) {
        g_partials[bid] = sm.red[0];
        __threadfence();
        unsigned int r = atomicAdd(&g_count, 1u);
        sm.s_last = (r == (unsigned)(kGrid - 1));
    }
    __syncthreads();

    if (sm.s_last) {
        float s = 0.0f;
        for (int p = tid; p < kGrid; p += 256) s += __ldcg(&g_partials[p]);
        sm.red[tid] = s;
        __syncthreads();
#pragma unroll
        for (int s2 = 128; s2 > 0; s2 >>= 1) {
            if (tid < s2) sm.red[tid] += sm.red[tid + s2];
            __syncthreads();
        }
        if (tid == 0) {
            loss[0] = sm.red[0];
            g_count = 0;
        }
        for (int p = 1 + tid; p < out_size; p += 256) loss[p] = 0.0f;
    }
}

extern "C" void kernel_launch(void* const* d_in, const int* in_sizes, int n_in,
                              void* d_out, int out_size) {
    const float* output = (const float*)d_in[0];
    const float* target = (const float*)d_in[1];
    k_fused<<<kGrid, 256>>>(output, target, (float*)d_out, out_size);
}